// round 16
// baseline (speedup 1.0000x reference)
#include <cuda_runtime.h>
#include <cstdint>
#include <math.h>

// ---------------------------------------------------------------------------
// Problem dims (fixed by dataset)
// ---------------------------------------------------------------------------
#define T_TOK 32768          // B*S tokens
#define H_DIM 768
#define I_DIM 3072
#define E_NUM 8
#define TP    (T_TOK * 2)    // total (token, expert-slot) rows, top-2
#define TROWS (TP + 1024)    // permuted row space, expert starts 128-aligned
#define MAX_TILES 520

// GEMM tiling: CTA 256x128, 512 threads, 16 warps (warp tile 64x32 — the
// shape R13/R15 validated). BM=256 halves B's L2-port traffic (19->14 GB
// total) and halves per-MMA loop/barrier overhead; L2 bandwidth is the
// co-binding limiter at the R13 shape (tensor% immovable at ~48% while
// occupancy/ILP changes did nothing).
#define BM 256
#define BN 128
#define BK 32
#define TILE_F 4096                     // floats per 128x32 tile (16 KB)
#define A_BYTES 32768                   // 256 rows x 32 floats
#define B_BYTES 16384
#define STG_BYTES (A_BYTES + B_BYTES)   // 49152
#define NSTAGE 3
#define GEMM_SMEM (STG_BYTES * NSTAGE)  // 147456 B -> 1 CTA (16 warps)/SM

// ---------------------------------------------------------------------------
// Scratch (device globals; no allocation allowed)
// ---------------------------------------------------------------------------
__device__ float g_xr[(size_t)T_TOK * H_DIM];              // tf32-rounded x (row-major)
__device__ float g_w1t[(size_t)E_NUM * 24 * 24 * TILE_F];  // w1^T tiled [e][nt][ks][tile]
__device__ float g_w2t[(size_t)E_NUM * 6 * 96 * TILE_F];   // w2^T tiled [e][nt][ks][tile]
__device__ float g_hmid[(size_t)96 * TROWS * 32];          // gelu out, k-chunk tiled [ks][p][32]
__device__ float g_y[(size_t)TROWS * H_DIM];               // hmid@w2+b2, permuted rows
__device__ int   g_permIdx[TROWS];
__device__ int   g_slotPos[TP];
__device__ float g_wts[TP];
__device__ int   g_sel[TP];
__device__ int   g_counts[E_NUM];
__device__ int   g_cursor[E_NUM];
__device__ int   g_tileE[MAX_TILES];
__device__ int   g_tileRow[MAX_TILES];
__device__ int   g_tileEnd[MAX_TILES];

// ---------------------------------------------------------------------------
// Helpers
// ---------------------------------------------------------------------------
__device__ __forceinline__ uint32_t smem_u32(const void* p) {
    uint32_t a;
    asm("{ .reg .u64 t; cvta.to.shared.u64 t, %1; cvt.u32.u64 %0, t; }" : "=r"(a) : "l"(p));
    return a;
}
__device__ __forceinline__ float to_tf32(float f) {
    float r; asm("cvt.rna.tf32.f32 %0, %1;" : "=f"(r) : "f"(f)); return r;
}
__device__ __forceinline__ float4 tf32x4(float4 v) {
    v.x = to_tf32(v.x); v.y = to_tf32(v.y); v.z = to_tf32(v.z); v.w = to_tf32(v.w);
    return v;
}
__device__ __forceinline__ float gelu_exact(float v) {
    return 0.5f * v * (1.0f + erff(v * 0.7071067811865476f));
}
// float index inside a swizzled 128-row x 32-float tile (XOR of 16B lanes);
// row is TILE-LOCAL (expert starts are 128-aligned so global r&7 == local&7)
__device__ __forceinline__ int swz(int row, int c) {
    return row * 32 + ((((c >> 2) ^ (row & 7)) << 2) | (c & 3));
}
__device__ __forceinline__ void cp16(uint32_t dst, const void* src) {
    asm volatile("cp.async.cg.shared.global [%0], [%1], 16;" :: "r"(dst), "l"(src));
}
__device__ __forceinline__ void bulk_g2s(uint32_t dst, const void* src, uint32_t bytes,
                                         uint32_t mbar) {
    asm volatile(
        "cp.async.bulk.shared::cluster.global.mbarrier::complete_tx::bytes "
        "[%0], [%1], %2, [%3];"
        :: "r"(dst), "l"(src), "r"(bytes), "r"(mbar) : "memory");
}
#define FENCE_PROXY_ASYNC() asm volatile("fence.proxy.async.shared::cta;" ::: "memory")
#define MBARRIER_INIT(addr, cnt) \
    asm volatile("mbarrier.init.shared.b64 [%0], %1;" :: "r"((uint32_t)(addr)), "r"((uint32_t)(cnt)) : "memory")
#define MBARRIER_EXPECT_TX(addr, tx) \
    asm volatile("mbarrier.arrive.expect_tx.shared.b64 _, [%0], %1;" :: "r"((uint32_t)(addr)), "r"((uint32_t)(tx)) : "memory")
#define MBARRIER_WAIT_PARITY(addr, par) do {                                              \
    uint32_t _m = (uint32_t)(addr), _p = (uint32_t)(par), _d;                             \
    asm volatile("{\n\t.reg .pred p;\n\t"                                                 \
        "mbarrier.try_wait.parity.acquire.cta.shared::cta.b64 p, [%1], %2;\n\t"           \
        "selp.b32 %0, 1, 0, p;\n\t}" : "=r"(_d) : "r"(_m), "r"(_p) : "memory");           \
    if (!_d) {                                                                            \
        asm volatile("{\n\t.reg .pred P1;\n\t"                                            \
            "WL_%=:\n\t"                                                                  \
            "mbarrier.try_wait.parity.acquire.cta.shared::cta.b64 P1, [%0], %1, 0x989680;\n\t" \
            "@P1 bra.uni WD_%=;\n\t"                                                      \
            "bra.uni WL_%=;\n\t"                                                          \
            "WD_%=:\n\t}" :: "r"(_m), "r"(_p) : "memory");                                \
    }                                                                                     \
} while (0)
__device__ __forceinline__ void mma_tf32(float* c, const uint32_t* a, const uint32_t* b) {
    asm volatile(
        "mma.sync.aligned.m16n8k8.row.col.f32.tf32.tf32.f32 "
        "{%0,%1,%2,%3}, {%4,%5,%6,%7}, {%8,%9}, {%0,%1,%2,%3};"
        : "+f"(c[0]), "+f"(c[1]), "+f"(c[2]), "+f"(c[3])
        : "r"(a[0]), "r"(a[1]), "r"(a[2]), "r"(a[3]), "r"(b[0]), "r"(b[1]));
}
__device__ __forceinline__ void ldsm4(uint32_t* d, uint32_t addr) {
    asm volatile("ldmatrix.sync.aligned.m8n8.x4.shared.b16 {%0,%1,%2,%3}, [%4];"
        : "=r"(d[0]), "=r"(d[1]), "=r"(d[2]), "=r"(d[3]) : "r"(addr));
}

// ---------------------------------------------------------------------------
// Kernel 0: router — logits, top-2, weights, counts; writes tf32-rounded x
// ---------------------------------------------------------------------------
__global__ void router_kernel(const float* __restrict__ x, const float* __restrict__ gw,
                              float* __restrict__ logits_out) {
    __shared__ float4 sg[E_NUM * 192];
    int tid = threadIdx.x;
    for (int i = tid; i < E_NUM * 192; i += 256) sg[i] = ((const float4*)gw)[i];
    __syncthreads();

    int warp = tid >> 5, lane = tid & 31;
    int t = blockIdx.x * 8 + warp;
    const float4* xr = (const float4*)(x + (size_t)t * H_DIM);
    float4* xo = (float4*)(g_xr + (size_t)t * H_DIM);

    float acc[E_NUM];
#pragma unroll
    for (int e = 0; e < E_NUM; e++) acc[e] = 0.f;

    for (int j = lane; j < 192; j += 32) {
        float4 xv = xr[j];
        xo[j] = tf32x4(xv);
#pragma unroll
        for (int e = 0; e < E_NUM; e++) {
            float4 g = sg[e * 192 + j];
            acc[e] += xv.x * g.x + xv.y * g.y + xv.z * g.z + xv.w * g.w;
        }
    }
#pragma unroll
    for (int off = 16; off > 0; off >>= 1)
#pragma unroll
        for (int e = 0; e < E_NUM; e++)
            acc[e] += __shfl_xor_sync(0xffffffffu, acc[e], off);

    if (lane == 0) {
        int i0 = 0; float l0 = acc[0];
#pragma unroll
        for (int e = 1; e < E_NUM; e++) if (acc[e] > l0) { l0 = acc[e]; i0 = e; }
        int i1 = -1; float l1 = -3.4e38f;
#pragma unroll
        for (int e = 0; e < E_NUM; e++)
            if (e != i0 && acc[e] > l1) { l1 = acc[e]; i1 = e; }
        float p1 = __expf(l1 - l0);
        float inv = 1.0f / (1.0f + p1);
        g_sel[2 * t] = i0;  g_sel[2 * t + 1] = i1;
        g_wts[2 * t] = inv; g_wts[2 * t + 1] = p1 * inv;
        atomicAdd(&g_counts[i0], 1);
        atomicAdd(&g_counts[i1], 1);
        float* lo = logits_out + (size_t)t * E_NUM;
#pragma unroll
        for (int e = 0; e < E_NUM; e++) lo[e] = acc[e];
    }
}

// ---------------------------------------------------------------------------
// Kernel 1: plan — expert starts ALIGNED to 128; tiles step BM=256
// ---------------------------------------------------------------------------
__global__ void plan_kernel() {
    if (threadIdx.x != 0 || blockIdx.x != 0) return;
    int s = 0, idx = 0;
    for (int e = 0; e < E_NUM; e++) {
        int c = g_counts[e];
        g_cursor[e] = s;
        int en = s + c;
        for (int r = s; r < en; r += BM) {
            g_tileE[idx] = e; g_tileRow[idx] = r; g_tileEnd[idx] = en; idx++;
        }
        s = (en + 127) & ~127;      // 128-align next expert's segment
    }
    for (; idx < MAX_TILES; idx++) g_tileE[idx] = -1;
}

// ---------------------------------------------------------------------------
// Kernel 2: prep — scatter + both weight transposes into TILED+SWIZZLED
// layout: w1t block (e, nt<24, ks<24), w2t block (e, nt<6, ks<96),
// each block = contiguous 16 KB 128x32 tile ready for cp.async.bulk.
// ---------------------------------------------------------------------------
__global__ void prep_kernel(const float* __restrict__ w1, const float* __restrict__ w2) {
    int z = blockIdx.z;
    int tx = threadIdx.x, ty = threadIdx.y;
    if (z < 16) {
        __shared__ float tile[32][33];
        int which = z >> 3, e = z & 7;
        const float* src = which ? w2 : w1;
        float* dst = which ? g_w2t : g_w1t;
        int R = which ? I_DIM : H_DIM;       // k-dim
        int C = which ? H_DIM : I_DIM;       // n-dim
        int c0 = (which ? blockIdx.y : blockIdx.x) * 32;   // n block
        int r0 = (which ? blockIdx.x : blockIdx.y) * 32;   // k block
        const float* s = src + (size_t)e * R * C;
#pragma unroll
        for (int j = 0; j < 32; j += 8)
            tile[ty + j][tx] = s[(size_t)(r0 + ty + j) * C + (c0 + tx)];
        __syncthreads();
        int ks = r0 >> 5;
#pragma unroll
        for (int j = 0; j < 32; j += 8) {
            int n = c0 + ty + j;
            int k = r0 + tx;
            int nt = n >> 7, row = n & 127, c = k & 31;
            size_t base = which ? ((((size_t)e * 6 + nt) * 96 + ks) << 12)
                                : ((((size_t)e * 24 + nt) * 24 + ks) << 12);
            dst[base + swz(row, c)] = to_tf32(tile[tx][ty + j]);
        }
    } else {
        int bid = blockIdx.y * gridDim.x + blockIdx.x;   // linearized
        if (bid >= T_TOK / 256) return;
        int t = bid * 256 + ty * 32 + tx;
#pragma unroll
        for (int k = 0; k < 2; k++) {
            int e = g_sel[2 * t + k];
            int pos = atomicAdd(&g_cursor[e], 1);
            g_permIdx[pos] = t;
            g_slotPos[2 * t + k] = pos;
        }
    }
}

// ---------------------------------------------------------------------------
// Kernel 3: grouped GEMM, mma.sync tf32, CTA 256x128, 512 threads, 16 warps
// (warp grid 4x4, warp tile 64x32), 3-stage bulk pipeline, 1 CTA/SM.
//   mode 0: hmid[p] = tf32(gelu(xr[perm[p]] @ w1t^T + b1))   K=768,  NTOT=3072
//   mode 1: y[p]    = hmid[p] @ w2t^T + b2                   K=3072, NTOT=768
// ---------------------------------------------------------------------------
__global__ void __launch_bounds__(512, 1)
moe_gemm(int mode, const float* __restrict__ bias_all) {
    int tile = blockIdx.y;
    int e = g_tileE[tile];
    if (e < 0) return;

    const int K    = mode ? I_DIM : H_DIM;
    const int NTOT = mode ? H_DIM : I_DIM;
    const int NK   = K / BK;
    const int nt   = blockIdx.x;
    const int n0   = nt * BN;
    const int rowStart = g_tileRow[tile];   // multiple of 128 (aligned plan)
    const int rowEnd   = g_tileEnd[tile];

    extern __shared__ float sm[];
    __shared__ int   s_row[BM];
    __shared__ float s_bias[BN];
    __shared__ __align__(8) uint64_t s_mbar[NSTAGE];

    const int tid = threadIdx.x;
    const int wid = tid >> 5, lane = tid & 31;
    const int wm = wid >> 2, wn = wid & 3;       // warp grid 4 x 4, warp tile 64x32
    const int g = lane >> 2, tig = lane & 3;
    const int q = lane >> 3, r8 = lane & 7;
    const int qh = q >> 1, ql = q & 1;

    // B tile stream base (floats): tiled blocks [e][nt][ks]
    const float* bTile = mode ? (g_w2t + ((((size_t)e * 6 + nt) * 96) << 12))
                              : (g_w1t + ((((size_t)e * 24 + nt) * 24) << 12));
    // A bulk stream (mode 1): k-chunk tiled hmid, rows rowStart..rowStart+255
    const float* aBulk = g_hmid + (size_t)rowStart * 32;

    if (tid == 0) {
#pragma unroll
        for (int s = 0; s < NSTAGE; s++) MBARRIER_INIT(smem_u32(&s_mbar[s]), 1);
        FENCE_PROXY_ASYNC();
    }
    if (!mode && tid < BM) {
        int r = rowStart + tid;
        int rr = (r < rowEnd) ? r : rowStart;     // clamp loads; stores predicated later
        s_row[tid] = g_permIdx[rr];
    }
    if (tid < BN) s_bias[tid] = bias_all[(size_t)e * NTOT + n0 + tid];
    __syncthreads();

    const uint32_t suA = smem_u32(sm);
    uint32_t mb[NSTAGE];
#pragma unroll
    for (int s = 0; s < NSTAGE; s++) mb[s] = smem_u32(&s_mbar[s]);

    // mode-0 A gather: 2 threads per row (512 threads, 256 rows), 64 B each
    const int ar = tid >> 1, ah = tid & 1;
    const float* aRow = mode ? (const float*)nullptr
                             : g_xr + (size_t)s_row[ar] * H_DIM + ah * 16;
    const uint32_t aDstRow = suA + (uint32_t)(ar * 128);

#define ISSUE_STAGE(ks)                                                        \
    do {                                                                       \
        int _s = (ks) % NSTAGE;                                                \
        uint32_t _sb = (uint32_t)(_s * STG_BYTES);                             \
        if (tid == 0) {                                                        \
            MBARRIER_EXPECT_TX(mb[_s], mode ? (A_BYTES + B_BYTES) : B_BYTES);  \
            bulk_g2s(suA + _sb + A_BYTES, bTile + ((size_t)(ks) << 12),        \
                     B_BYTES, mb[_s]);                                         \
            if (mode) bulk_g2s(suA + _sb, aBulk + (size_t)(ks) * (TROWS * 32), \
                               A_BYTES, mb[_s]);                               \
        }                                                                      \
        if (!mode) {                                                           \
            const float* _ap = aRow + (ks) * BK;                               \
            _Pragma("unroll")                                                  \
            for (int j = 0; j < 4; j++)                                        \
                cp16(aDstRow + _sb + ((uint32_t)(((ah * 4 + j) ^ (ar & 7)) << 4)), \
                     _ap + j * 4);                                             \
            asm volatile("cp.async.commit_group;" ::: "memory");               \
        }                                                                      \
    } while (0)

    // ldmatrix row offsets (bytes within a tile)
    uint32_t aOff[4], bOff[2];
#pragma unroll
    for (int mt = 0; mt < 4; mt++)
        aOff[mt] = (uint32_t)((wm * 64 + mt * 16 + ql * 8 + r8) * 128);
#pragma unroll
    for (int np = 0; np < 2; np++)
        bOff[np] = (uint32_t)((wn * 32 + np * 16 + qh * 8 + r8) * 128);

    float acc[4][4][4];
#pragma unroll
    for (int mt = 0; mt < 4; mt++)
#pragma unroll
        for (int ntl = 0; ntl < 4; ntl++)
#pragma unroll
            for (int j = 0; j < 4; j++) acc[mt][ntl][j] = 0.f;

    ISSUE_STAGE(0);
    ISSUE_STAGE(1);

    for (int ks = 0; ks < NK; ks++) {
        if (!mode) {
            if (ks < NK - 1) asm volatile("cp.async.wait_group 1;" ::: "memory");
            else             asm volatile("cp.async.wait_group 0;" ::: "memory");
        }
        MBARRIER_WAIT_PARITY(mb[ks % NSTAGE], (ks / NSTAGE) & 1);
        __syncthreads();                        // all copies done, slot free
        if (ks + 2 < NK) ISSUE_STAGE(ks + 2);

        const uint32_t sA = suA + (uint32_t)((ks % NSTAGE) * STG_BYTES);
        const uint32_t sB = sA + A_BYTES;

#pragma unroll
        for (int kk = 0; kk < 4; kk++) {
            const uint32_t xa = (uint32_t)(((kk * 2 + qh) ^ r8) << 4);
            const uint32_t xb = (uint32_t)(((kk * 2 + ql) ^ r8) << 4);
            uint32_t a[4][4], b[2][4];
#pragma unroll
            for (int mt = 0; mt < 4; mt++) ldsm4(a[mt], sA + aOff[mt] + xa);
#pragma unroll
            for (int np = 0; np < 2; np++) ldsm4(b[np], sB + bOff[np] + xb);
#pragma unroll
            for (int mt = 0; mt < 4; mt++)
#pragma unroll
                for (int ntl = 0; ntl < 4; ntl++)
                    mma_tf32(acc[mt][ntl], a[mt], &b[ntl >> 1][(ntl & 1) * 2]);
        }
    }

    // Epilogue
    if (mode == 0) {
        // gelu+tf32 into k-chunk tiled g_hmid (chunk fixed per warp);
        // r&7 == tile-local&7 because rowStart is 128-aligned
        int chunk = (n0 >> 5) + wn;
#pragma unroll
        for (int mt = 0; mt < 4; mt++) {
#pragma unroll
            for (int i = 0; i < 2; i++) {
                int r = rowStart + wm * 64 + mt * 16 + g + i * 8;
                if (r >= rowEnd) continue;
                float* cb2 = g_hmid + ((size_t)chunk * TROWS + r) * 32;
#pragma unroll
                for (int ntl = 0; ntl < 4; ntl++) {
                    int cc = ntl * 8 + tig * 2;
                    float v0 = acc[mt][ntl][i * 2 + 0] + s_bias[wn * 32 + cc];
                    float v1 = acc[mt][ntl][i * 2 + 1] + s_bias[wn * 32 + cc + 1];
                    v0 = to_tf32(gelu_exact(v0));
                    v1 = to_tf32(gelu_exact(v1));
                    int idx = ((((cc >> 2) ^ (r & 7)) << 2) | (cc & 3));
                    *(float2*)(cb2 + idx) = make_float2(v0, v1);
                }
            }
        }
    } else {
#pragma unroll
        for (int mt = 0; mt < 4; mt++) {
#pragma unroll
            for (int i = 0; i < 2; i++) {
                int r = rowStart + wm * 64 + mt * 16 + g + i * 8;
                if (r >= rowEnd) continue;
                float* drow = g_y + (size_t)r * H_DIM + n0;
#pragma unroll
                for (int ntl = 0; ntl < 4; ntl++) {
                    int c = wn * 32 + ntl * 8 + tig * 2;
                    float v0 = acc[mt][ntl][i * 2 + 0] + s_bias[c];
                    float v1 = acc[mt][ntl][i * 2 + 1] + s_bias[c + 1];
                    *(float2*)(drow + c) = make_float2(v0, v1);
                }
            }
        }
    }
#undef ISSUE_STAGE
}

// ---------------------------------------------------------------------------
// Kernel 5: combine — out[t] = w0*y[pos0] + w1*y[pos1]
// ---------------------------------------------------------------------------
__global__ void combine_kernel(float* __restrict__ out) {
    int t = blockIdx.x;
    int p0 = g_slotPos[2 * t], p1 = g_slotPos[2 * t + 1];
    float w0 = g_wts[2 * t], w1 = g_wts[2 * t + 1];
    const float4* y0 = (const float4*)(g_y + (size_t)p0 * H_DIM);
    const float4* y1 = (const float4*)(g_y + (size_t)p1 * H_DIM);
    float4* o = (float4*)(out + (size_t)t * H_DIM);
    int i = threadIdx.x;
    float4 a = y0[i], b = y1[i];
    o[i] = make_float4(w0 * a.x + w1 * b.x, w0 * a.y + w1 * b.y,
                       w0 * a.z + w1 * b.z, w0 * a.w + w1 * b.w);
}

// ---------------------------------------------------------------------------
// Launch — moe_gemm(0) stays at kernel launch index 3 (ncu window)
// ---------------------------------------------------------------------------
extern "C" void kernel_launch(void* const* d_in, const int* in_sizes, int n_in,
                              void* d_out, int out_size) {
    const float* x  = (const float*)d_in[0];  // hidden_states [B,S,H]
    const float* gw = (const float*)d_in[1];  // gate_w [E,H]
    const float* w1 = (const float*)d_in[2];  // [E,H,I]
    const float* b1 = (const float*)d_in[3];  // [E,I]
    const float* w2 = (const float*)d_in[4];  // [E,I,H]
    const float* b2 = (const float*)d_in[5];  // [E,H]
    float* out = (float*)d_out;
    float* logits = out + ((size_t)out_size - (size_t)T_TOK * E_NUM);

    (void)cudaGetLastError();   // scrub any stale sticky error from env flake

    cudaFuncSetAttribute(moe_gemm, cudaFuncAttributeMaxDynamicSharedMemorySize, GEMM_SMEM);

    void* countsPtr = nullptr;
    cudaGetSymbolAddress(&countsPtr, g_counts);
    cudaMemsetAsync(countsPtr, 0, E_NUM * sizeof(int));         // memset node

    router_kernel<<<T_TOK / 8, 256>>>(x, gw, logits);           // k0
    plan_kernel<<<1, 32>>>();                                   // k1
    prep_kernel<<<dim3(96, 24, 17), dim3(32, 8)>>>(w1, w2);     // k2
    moe_gemm<<<dim3(I_DIM / BN, MAX_TILES), 512, GEMM_SMEM>>>(0, b1);  // k3 <- profiled
    moe_gemm<<<dim3(H_DIM / BN, MAX_TILES), 512, GEMM_SMEM>>>(1, b2);  // k4
    combine_kernel<<<T_TOK, 192>>>(out);                        // k5
}

// round 17
// speedup vs baseline: 1.2574x; 1.2574x over previous
#include <cuda_runtime.h>
#include <cstdint>
#include <math.h>

// ---------------------------------------------------------------------------
// Problem dims (fixed by dataset)
// ---------------------------------------------------------------------------
#define T_TOK 32768          // B*S tokens
#define H_DIM 768
#define I_DIM 3072
#define E_NUM 8
#define TP    (T_TOK * 2)    // total (token, expert-slot) rows, top-2
#define TROWS (TP + 1024)    // permuted row space, expert starts 128-aligned
#define MAX_TILES 520

// GEMM tiling: R13 shape (BM=128, BN=128, 2 CTAs/SM — validated optimum of
// this family; R14/R16 tile reshapes both regressed). NEW: A is PRE-GATHERED
// once into a bulk-able tiled layout (g_xg), so BOTH modes stream A and B
// with one cp.async.bulk per stage — the 304M-LDGSTS mode-0 gather storm
// (~2.3ms of SMSP issue occupancy, 24x redundant per tile) is gone.
#define BM 128
#define BN 128
#define BK 32
#define TILE_F 4096                     // floats per 128x32 tile (16 KB)
#define STG_BYTES 32768                 // A tile + B tile per stage
#define NSTAGE 3
#define GEMM_SMEM (STG_BYTES * NSTAGE)  // 98304 B -> 2 CTAs/SM

// ---------------------------------------------------------------------------
// Scratch (device globals; no allocation allowed)
// ---------------------------------------------------------------------------
__device__ float g_xr[(size_t)T_TOK * H_DIM];              // tf32-rounded x (row-major)
__device__ float g_xg[(size_t)24 * TROWS * 32];            // permuted A, k-chunk tiled
__device__ float g_w1t[(size_t)E_NUM * 24 * 24 * TILE_F];  // w1^T tiled [e][nt][ks][tile]
__device__ float g_w2t[(size_t)E_NUM * 6 * 96 * TILE_F];   // w2^T tiled [e][nt][ks][tile]
__device__ float g_hmid[(size_t)96 * TROWS * 32];          // gelu out, k-chunk tiled
__device__ float g_y[(size_t)TROWS * H_DIM];               // hmid@w2+b2, permuted rows
__device__ int   g_permIdx[TROWS];
__device__ int   g_slotPos[TP];
__device__ float g_wts[TP];
__device__ int   g_sel[TP];
__device__ int   g_counts[E_NUM];
__device__ int   g_cursor[E_NUM];
__device__ int   g_tileE[MAX_TILES];
__device__ int   g_tileRow[MAX_TILES];
__device__ int   g_tileEnd[MAX_TILES];

// ---------------------------------------------------------------------------
// Helpers
// ---------------------------------------------------------------------------
__device__ __forceinline__ uint32_t smem_u32(const void* p) {
    uint32_t a;
    asm("{ .reg .u64 t; cvta.to.shared.u64 t, %1; cvt.u32.u64 %0, t; }" : "=r"(a) : "l"(p));
    return a;
}
__device__ __forceinline__ float to_tf32(float f) {
    float r; asm("cvt.rna.tf32.f32 %0, %1;" : "=f"(r) : "f"(f)); return r;
}
__device__ __forceinline__ float4 tf32x4(float4 v) {
    v.x = to_tf32(v.x); v.y = to_tf32(v.y); v.z = to_tf32(v.z); v.w = to_tf32(v.w);
    return v;
}
__device__ __forceinline__ float gelu_exact(float v) {
    return 0.5f * v * (1.0f + erff(v * 0.7071067811865476f));
}
// float index inside a swizzled 128-row x 32-float tile (XOR of 16B lanes);
// row is TILE-LOCAL (expert starts are 128-aligned so global r&7 == local&7)
__device__ __forceinline__ int swz(int row, int c) {
    return row * 32 + ((((c >> 2) ^ (row & 7)) << 2) | (c & 3));
}
__device__ __forceinline__ void bulk_g2s(uint32_t dst, const void* src, uint32_t bytes,
                                         uint32_t mbar) {
    asm volatile(
        "cp.async.bulk.shared::cluster.global.mbarrier::complete_tx::bytes "
        "[%0], [%1], %2, [%3];"
        :: "r"(dst), "l"(src), "r"(bytes), "r"(mbar) : "memory");
}
#define FENCE_PROXY_ASYNC() asm volatile("fence.proxy.async.shared::cta;" ::: "memory")
#define MBARRIER_INIT(addr, cnt) \
    asm volatile("mbarrier.init.shared.b64 [%0], %1;" :: "r"((uint32_t)(addr)), "r"((uint32_t)(cnt)) : "memory")
#define MBARRIER_EXPECT_TX(addr, tx) \
    asm volatile("mbarrier.arrive.expect_tx.shared.b64 _, [%0], %1;" :: "r"((uint32_t)(addr)), "r"((uint32_t)(tx)) : "memory")
#define MBARRIER_WAIT_PARITY(addr, par) do {                                              \
    uint32_t _m = (uint32_t)(addr), _p = (uint32_t)(par), _d;                             \
    asm volatile("{\n\t.reg .pred p;\n\t"                                                 \
        "mbarrier.try_wait.parity.acquire.cta.shared::cta.b64 p, [%1], %2;\n\t"           \
        "selp.b32 %0, 1, 0, p;\n\t}" : "=r"(_d) : "r"(_m), "r"(_p) : "memory");           \
    if (!_d) {                                                                            \
        asm volatile("{\n\t.reg .pred P1;\n\t"                                            \
            "WL_%=:\n\t"                                                                  \
            "mbarrier.try_wait.parity.acquire.cta.shared::cta.b64 P1, [%0], %1, 0x989680;\n\t" \
            "@P1 bra.uni WD_%=;\n\t"                                                      \
            "bra.uni WL_%=;\n\t"                                                          \
            "WD_%=:\n\t}" :: "r"(_m), "r"(_p) : "memory");                                \
    }                                                                                     \
} while (0)
__device__ __forceinline__ void mma_tf32(float* c, const uint32_t* a, const uint32_t* b) {
    asm volatile(
        "mma.sync.aligned.m16n8k8.row.col.f32.tf32.tf32.f32 "
        "{%0,%1,%2,%3}, {%4,%5,%6,%7}, {%8,%9}, {%0,%1,%2,%3};"
        : "+f"(c[0]), "+f"(c[1]), "+f"(c[2]), "+f"(c[3])
        : "r"(a[0]), "r"(a[1]), "r"(a[2]), "r"(a[3]), "r"(b[0]), "r"(b[1]));
}
__device__ __forceinline__ void ldsm4(uint32_t* d, uint32_t addr) {
    asm volatile("ldmatrix.sync.aligned.m8n8.x4.shared.b16 {%0,%1,%2,%3}, [%4];"
        : "=r"(d[0]), "=r"(d[1]), "=r"(d[2]), "=r"(d[3]) : "r"(addr));
}

// ---------------------------------------------------------------------------
// Kernel 0: router — logits, top-2, weights, counts; writes tf32-rounded x
// ---------------------------------------------------------------------------
__global__ void router_kernel(const float* __restrict__ x, const float* __restrict__ gw,
                              float* __restrict__ logits_out) {
    __shared__ float4 sg[E_NUM * 192];
    int tid = threadIdx.x;
    for (int i = tid; i < E_NUM * 192; i += 256) sg[i] = ((const float4*)gw)[i];
    __syncthreads();

    int warp = tid >> 5, lane = tid & 31;
    int t = blockIdx.x * 8 + warp;
    const float4* xr = (const float4*)(x + (size_t)t * H_DIM);
    float4* xo = (float4*)(g_xr + (size_t)t * H_DIM);

    float acc[E_NUM];
#pragma unroll
    for (int e = 0; e < E_NUM; e++) acc[e] = 0.f;

    for (int j = lane; j < 192; j += 32) {
        float4 xv = xr[j];
        xo[j] = tf32x4(xv);
#pragma unroll
        for (int e = 0; e < E_NUM; e++) {
            float4 g = sg[e * 192 + j];
            acc[e] += xv.x * g.x + xv.y * g.y + xv.z * g.z + xv.w * g.w;
        }
    }
#pragma unroll
    for (int off = 16; off > 0; off >>= 1)
#pragma unroll
        for (int e = 0; e < E_NUM; e++)
            acc[e] += __shfl_xor_sync(0xffffffffu, acc[e], off);

    if (lane == 0) {
        int i0 = 0; float l0 = acc[0];
#pragma unroll
        for (int e = 1; e < E_NUM; e++) if (acc[e] > l0) { l0 = acc[e]; i0 = e; }
        int i1 = -1; float l1 = -3.4e38f;
#pragma unroll
        for (int e = 0; e < E_NUM; e++)
            if (e != i0 && acc[e] > l1) { l1 = acc[e]; i1 = e; }
        float p1 = __expf(l1 - l0);
        float inv = 1.0f / (1.0f + p1);
        g_sel[2 * t] = i0;  g_sel[2 * t + 1] = i1;
        g_wts[2 * t] = inv; g_wts[2 * t + 1] = p1 * inv;
        atomicAdd(&g_counts[i0], 1);
        atomicAdd(&g_counts[i1], 1);
        float* lo = logits_out + (size_t)t * E_NUM;
#pragma unroll
        for (int e = 0; e < E_NUM; e++) lo[e] = acc[e];
    }
}

// ---------------------------------------------------------------------------
// Kernel 1: plan — expert starts ALIGNED to 128 (swizzle-phase + bulk-align)
// ---------------------------------------------------------------------------
__global__ void plan_kernel() {
    if (threadIdx.x != 0 || blockIdx.x != 0) return;
    int s = 0, idx = 0;
    for (int e = 0; e < E_NUM; e++) {
        int c = g_counts[e];
        g_cursor[e] = s;
        int en = s + c;
        for (int r = s; r < en; r += BM) {
            g_tileE[idx] = e; g_tileRow[idx] = r; g_tileEnd[idx] = en; idx++;
        }
        s = (en + 127) & ~127;      // 128-align next expert's segment
    }
    for (; idx < MAX_TILES; idx++) g_tileE[idx] = -1;
}

// ---------------------------------------------------------------------------
// Kernel 2: prep — scatter + both weight transposes into TILED+SWIZZLED
// layout: w1t block (e, nt<24, ks<24), w2t block (e, nt<6, ks<96),
// each block = contiguous 16 KB 128x32 tile ready for cp.async.bulk.
// ---------------------------------------------------------------------------
__global__ void prep_kernel(const float* __restrict__ w1, const float* __restrict__ w2) {
    int z = blockIdx.z;
    int tx = threadIdx.x, ty = threadIdx.y;
    if (z < 16) {
        __shared__ float tile[32][33];
        int which = z >> 3, e = z & 7;
        const float* src = which ? w2 : w1;
        float* dst = which ? g_w2t : g_w1t;
        int R = which ? I_DIM : H_DIM;       // k-dim
        int C = which ? H_DIM : I_DIM;       // n-dim
        int c0 = (which ? blockIdx.y : blockIdx.x) * 32;   // n block
        int r0 = (which ? blockIdx.x : blockIdx.y) * 32;   // k block
        const float* s = src + (size_t)e * R * C;
#pragma unroll
        for (int j = 0; j < 32; j += 8)
            tile[ty + j][tx] = s[(size_t)(r0 + ty + j) * C + (c0 + tx)];
        __syncthreads();
        int ks = r0 >> 5;
#pragma unroll
        for (int j = 0; j < 32; j += 8) {
            int n = c0 + ty + j;
            int k = r0 + tx;
            int nt = n >> 7, row = n & 127, c = k & 31;
            size_t base = which ? ((((size_t)e * 6 + nt) * 96 + ks) << 12)
                                : ((((size_t)e * 24 + nt) * 24 + ks) << 12);
            dst[base + swz(row, c)] = to_tf32(tile[tx][ty + j]);
        }
    } else {
        int bid = blockIdx.y * gridDim.x + blockIdx.x;   // linearized
        if (bid >= T_TOK / 256) return;
        int t = bid * 256 + ty * 32 + tx;
#pragma unroll
        for (int k = 0; k < 2; k++) {
            int e = g_sel[2 * t + k];
            int pos = atomicAdd(&g_cursor[e], 1);
            g_permIdx[pos] = t;
            g_slotPos[2 * t + k] = pos;
        }
    }
}

// ---------------------------------------------------------------------------
// Kernel 3: gatherA — ONE pass materializing the permuted A in k-chunk tiled
// + swizzled layout [ks<24][p][32] so moe_gemm(0) can bulk-copy it (this
// replaces 304M in-GEMM LDGSTS with 12.6M loads issued once).
// grid (MAX_TILES, 24), block 256: 2 threads per row, 16 floats each.
// ---------------------------------------------------------------------------
__global__ void gatherA() {
    int tile = blockIdx.x;
    int e = g_tileE[tile];
    if (e < 0) return;
    int rowStart = g_tileRow[tile];
    int rowEnd   = g_tileEnd[tile];
    int chunk = blockIdx.y;

    int tid = threadIdx.x;
    int p = rowStart + (tid >> 1);
    if (p >= rowEnd) return;                 // padding rows stay 0 (never read live)
    int half = tid & 1;
    int tok = g_permIdx[p];

    const float4* src = (const float4*)(g_xr + (size_t)tok * H_DIM + chunk * 32 + half * 16);
    float* dst = g_xg + ((size_t)chunk * TROWS + p) * 32;
#pragma unroll
    for (int j = 0; j < 4; j++) {
        int c4 = half * 4 + j;               // float4 index within the 32-float row
        dst[((c4 ^ (p & 7)) << 2)] = src[j].x;     // swizzled 16B lane
        dst[((c4 ^ (p & 7)) << 2) + 1] = src[j].y;
        dst[((c4 ^ (p & 7)) << 2) + 2] = src[j].z;
        dst[((c4 ^ (p & 7)) << 2) + 3] = src[j].w;
    }
}

// ---------------------------------------------------------------------------
// Kernel 4: grouped GEMM, mma.sync tf32, CTA 128x128, 8 warps (64x32),
// 3-stage pipeline, 2 CTAs/SM. BOTH operands arrive via cp.async.bulk in
// BOTH modes (A source: g_xg for mode 0, g_hmid for mode 1) — no LDGSTS.
//   mode 0: hmid[p] = tf32(gelu(A0[p] @ w1t^T + b1))   K=768,  NTOT=3072
//   mode 1: y[p]    = hmid[p] @ w2t^T + b2             K=3072, NTOT=768
// ---------------------------------------------------------------------------
__global__ void __launch_bounds__(256, 2)
moe_gemm(int mode, const float* __restrict__ bias_all) {
    int tile = blockIdx.y;
    int e = g_tileE[tile];
    if (e < 0) return;

    const int NTOT = mode ? H_DIM : I_DIM;
    const int NK   = (mode ? I_DIM : H_DIM) / BK;
    const int nt   = blockIdx.x;
    const int n0   = nt * BN;
    const int rowStart = g_tileRow[tile];   // multiple of 128 (aligned plan)
    const int rowEnd   = g_tileEnd[tile];

    extern __shared__ float sm[];
    __shared__ float s_bias[BN];
    __shared__ __align__(8) uint64_t s_mbar[NSTAGE];

    const int tid = threadIdx.x;
    const int wid = tid >> 5, lane = tid & 31;
    const int wm = wid >> 2, wn = wid & 3;       // warp grid 2 x 4, warp tile 64x32
    const int g = lane >> 2, tig = lane & 3;
    const int q = lane >> 3, r8 = lane & 7;
    const int qh = q >> 1, ql = q & 1;

    // streams: tiled blocks, both bulk-able
    const float* bTile = mode ? (g_w2t + ((((size_t)e * 6 + nt) * 96) << 12))
                              : (g_w1t + ((((size_t)e * 24 + nt) * 24) << 12));
    const float* aBulk = (mode ? g_hmid : g_xg) + (size_t)rowStart * 32;

    if (tid == 0) {
#pragma unroll
        for (int s = 0; s < NSTAGE; s++) MBARRIER_INIT(smem_u32(&s_mbar[s]), 1);
        FENCE_PROXY_ASYNC();
    }
    if (tid < BN) s_bias[tid] = bias_all[(size_t)e * NTOT + n0 + tid];
    __syncthreads();

    const uint32_t suA = smem_u32(sm);
    uint32_t mb[NSTAGE];
#pragma unroll
    for (int s = 0; s < NSTAGE; s++) mb[s] = smem_u32(&s_mbar[s]);

#define ISSUE_STAGE(ks)                                                        \
    do {                                                                       \
        int _s = (ks) % NSTAGE;                                                \
        uint32_t _sb = (uint32_t)(_s * STG_BYTES);                             \
        if (tid == 0) {                                                        \
            MBARRIER_EXPECT_TX(mb[_s], 32768u);                                \
            bulk_g2s(suA + _sb + 16384, bTile + ((size_t)(ks) << 12), 16384, mb[_s]); \
            bulk_g2s(suA + _sb, aBulk + (size_t)(ks) * (TROWS * 32), 16384, mb[_s]); \
        }                                                                      \
    } while (0)

    // ldmatrix row offsets (bytes within a tile)
    uint32_t aOff[4], bOff[2];
#pragma unroll
    for (int mt = 0; mt < 4; mt++)
        aOff[mt] = (uint32_t)((wm * 64 + mt * 16 + ql * 8 + r8) * 128);
#pragma unroll
    for (int np = 0; np < 2; np++)
        bOff[np] = (uint32_t)((wn * 32 + np * 16 + qh * 8 + r8) * 128);

    float acc[4][4][4];
#pragma unroll
    for (int mt = 0; mt < 4; mt++)
#pragma unroll
        for (int ntl = 0; ntl < 4; ntl++)
#pragma unroll
            for (int j = 0; j < 4; j++) acc[mt][ntl][j] = 0.f;

    ISSUE_STAGE(0);
    ISSUE_STAGE(1);

    for (int ks = 0; ks < NK; ks++) {
        MBARRIER_WAIT_PARITY(mb[ks % NSTAGE], (ks / NSTAGE) & 1);
        __syncthreads();                        // stage ks-1 consumed, slot free
        if (ks + 2 < NK) ISSUE_STAGE(ks + 2);

        const uint32_t sA = suA + (uint32_t)((ks % NSTAGE) * STG_BYTES);
        const uint32_t sB = sA + 16384;

#pragma unroll
        for (int kk = 0; kk < 4; kk++) {
            const uint32_t xa = (uint32_t)(((kk * 2 + qh) ^ r8) << 4);
            const uint32_t xb = (uint32_t)(((kk * 2 + ql) ^ r8) << 4);
            uint32_t a[4][4], b[2][4];
#pragma unroll
            for (int mt = 0; mt < 4; mt++) ldsm4(a[mt], sA + aOff[mt] + xa);
#pragma unroll
            for (int np = 0; np < 2; np++) ldsm4(b[np], sB + bOff[np] + xb);
#pragma unroll
            for (int mt = 0; mt < 4; mt++)
#pragma unroll
                for (int ntl = 0; ntl < 4; ntl++)
                    mma_tf32(acc[mt][ntl], a[mt], &b[ntl >> 1][(ntl & 1) * 2]);
        }
    }

    // Epilogue
    if (mode == 0) {
        // gelu+tf32 into k-chunk tiled g_hmid (chunk fixed per warp);
        // r&7 == tile-local&7 because rowStart is 128-aligned
        int chunk = (n0 >> 5) + wn;
#pragma unroll
        for (int mt = 0; mt < 4; mt++) {
#pragma unroll
            for (int i = 0; i < 2; i++) {
                int r = rowStart + wm * 64 + mt * 16 + g + i * 8;
                if (r >= rowEnd) continue;
                float* cb2 = g_hmid + ((size_t)chunk * TROWS + r) * 32;
#pragma unroll
                for (int ntl = 0; ntl < 4; ntl++) {
                    int cc = ntl * 8 + tig * 2;
                    float v0 = acc[mt][ntl][i * 2 + 0] + s_bias[wn * 32 + cc];
                    float v1 = acc[mt][ntl][i * 2 + 1] + s_bias[wn * 32 + cc + 1];
                    v0 = to_tf32(gelu_exact(v0));
                    v1 = to_tf32(gelu_exact(v1));
                    int idx = ((((cc >> 2) ^ (r & 7)) << 2) | (cc & 3));
                    *(float2*)(cb2 + idx) = make_float2(v0, v1);
                }
            }
        }
    } else {
#pragma unroll
        for (int mt = 0; mt < 4; mt++) {
#pragma unroll
            for (int i = 0; i < 2; i++) {
                int r = rowStart + wm * 64 + mt * 16 + g + i * 8;
                if (r >= rowEnd) continue;
                float* drow = g_y + (size_t)r * H_DIM + n0;
#pragma unroll
                for (int ntl = 0; ntl < 4; ntl++) {
                    int c = wn * 32 + ntl * 8 + tig * 2;
                    float v0 = acc[mt][ntl][i * 2 + 0] + s_bias[c];
                    float v1 = acc[mt][ntl][i * 2 + 1] + s_bias[c + 1];
                    *(float2*)(drow + c) = make_float2(v0, v1);
                }
            }
        }
    }
#undef ISSUE_STAGE
}

// ---------------------------------------------------------------------------
// Kernel 6: combine — out[t] = w0*y[pos0] + w1*y[pos1]
// ---------------------------------------------------------------------------
__global__ void combine_kernel(float* __restrict__ out) {
    int t = blockIdx.x;
    int p0 = g_slotPos[2 * t], p1 = g_slotPos[2 * t + 1];
    float w0 = g_wts[2 * t], w1 = g_wts[2 * t + 1];
    const float4* y0 = (const float4*)(g_y + (size_t)p0 * H_DIM);
    const float4* y1 = (const float4*)(g_y + (size_t)p1 * H_DIM);
    float4* o = (float4*)(out + (size_t)t * H_DIM);
    int i = threadIdx.x;
    float4 a = y0[i], b = y1[i];
    o[i] = make_float4(w0 * a.x + w1 * b.x, w0 * a.y + w1 * b.y,
                       w0 * a.z + w1 * b.z, w0 * a.w + w1 * b.w);
}

// ---------------------------------------------------------------------------
// Launch
// ---------------------------------------------------------------------------
extern "C" void kernel_launch(void* const* d_in, const int* in_sizes, int n_in,
                              void* d_out, int out_size) {
    const float* x  = (const float*)d_in[0];  // hidden_states [B,S,H]
    const float* gw = (const float*)d_in[1];  // gate_w [E,H]
    const float* w1 = (const float*)d_in[2];  // [E,H,I]
    const float* b1 = (const float*)d_in[3];  // [E,I]
    const float* w2 = (const float*)d_in[4];  // [E,I,H]
    const float* b2 = (const float*)d_in[5];  // [E,H]
    float* out = (float*)d_out;
    float* logits = out + ((size_t)out_size - (size_t)T_TOK * E_NUM);

    (void)cudaGetLastError();   // scrub any stale sticky error from env flake

    cudaFuncSetAttribute(moe_gemm, cudaFuncAttributeMaxDynamicSharedMemorySize, GEMM_SMEM);

    void* countsPtr = nullptr;
    cudaGetSymbolAddress(&countsPtr, g_counts);
    cudaMemsetAsync(countsPtr, 0, E_NUM * sizeof(int));         // memset node

    router_kernel<<<T_TOK / 8, 256>>>(x, gw, logits);           // k0
    plan_kernel<<<1, 32>>>();                                   // k1
    prep_kernel<<<dim3(96, 24, 17), dim3(32, 8)>>>(w1, w2);     // k2
    gatherA<<<dim3(MAX_TILES, 24), 256>>>();                    // k3
    moe_gemm<<<dim3(I_DIM / BN, MAX_TILES), 256, GEMM_SMEM>>>(0, b1);  // k4
    moe_gemm<<<dim3(H_DIM / BN, MAX_TILES), 256, GEMM_SMEM>>>(1, b2);  // k5
    combine_kernel<<<T_TOK, 192>>>(out);                        // k6
}